// round 11
// baseline (speedup 1.0000x reference)
#include <cuda_runtime.h>
#include <cstdint>

#define NNODES 50000
#define NEDGES 800000
#define FIN 256
#define HID 128
#define CAP 128              // bucket capacity per row (Poisson(16) edges/row)
#define GEMM_GRID ((NNODES + 63) / 64)                   // 782 (BM=64)
#define SCAT_GRID ((NEDGES + 1023) / 1024)               // 782 (256 thr x 4 edges)

// Scratch (no cudaMalloc); device symbols so kernel_launch is pure launches.
__device__ float g_S1[NNODES * HID];     // X @ W1
__device__ float g_H [NNODES * HID];     // relu(A @ S1 + b1)
__device__ float g_S2[NNODES * HID];     // H @ W2
__device__ int   g_cnt[NNODES];          // per-row edge count (bucket fill)
__device__ int2  g_edge[(size_t)NNODES * CAP];  // (col, val-bits) buckets

__device__ __forceinline__ uint32_t f2tf32(float f)
{
    uint32_t u;
    asm("cvt.rna.tf32.f32 %0, %1;" : "=r"(u) : "f"(f));
    return u;
}

// ---------------------------------------------------------------------------
// tf32 tensor GEMM body: C[M,128] = A[M,K] @ B[K,128]
// CTA tile 64x128 (BM=64 for occupancy: ~65 regs -> 3 CTAs/SM), BK=32,
// 8 warps (2m x 4n), warp tile 32x32, mma.m16n8k8 tf32.
// A smem quad-swizzled [64][32]; B smem padded [32][132]. ~25KB smem/CTA.
// ---------------------------------------------------------------------------
template <int K>
__device__ __forceinline__ void gemm_tf32_body(
    const float* __restrict__ A, const float* __restrict__ B,
    float* __restrict__ C, int bx)
{
    constexpr int BM = 64, BN = 128, BK = 32;
    constexpr int M = NNODES;
    __shared__ uint32_t As[BM][BK];       // quad-swizzled
    __shared__ uint32_t Bs[BK][BN + 4];   // padded

    const int tid  = threadIdx.x;
    const int wid  = tid >> 5;
    const int lane = tid & 31;
    const int g    = lane >> 2;
    const int t    = lane & 3;
    const int wm   = wid >> 2;            // 0..1 -> m offset wm*32
    const int wn   = wid & 3;             // 0..3 -> n offset wn*32
    const int bm0  = bx * BM;

    float acc[2][4][4];
#pragma unroll
    for (int i = 0; i < 2; i++)
#pragma unroll
        for (int j = 0; j < 4; j++)
#pragma unroll
            for (int e = 0; e < 4; e++) acc[i][j][e] = 0.f;

    // A tile: 64 rows x 8 quads = 512 float4; 2 per thread.
    const int a_row = tid >> 2;           // 0..63
    const int a_q0  = (tid & 3) * 2;      // quads {0,1},{2,3},{4,5},{6,7}
    // B tile: 32 rows x 32 quads = 1024 float4; 4 per thread.
    const int b_k   = tid >> 5;           // +i*8
    const int b_q   = tid & 31;

    for (int k0 = 0; k0 < K; k0 += BK) {
        // ---- A tile ----
        {
            const int gr = bm0 + a_row;
#pragma unroll
            for (int j = 0; j < 2; j++) {
                const int q = a_q0 + j;
                float4 v = make_float4(0.f, 0.f, 0.f, 0.f);
                if (gr < M)
                    v = *reinterpret_cast<const float4*>(A + (size_t)gr * K + k0 + q * 4);
                const int pq = q ^ (a_row & 7);
                uint32_t* dst = &As[a_row][pq * 4];
                dst[0] = f2tf32(v.x); dst[1] = f2tf32(v.y);
                dst[2] = f2tf32(v.z); dst[3] = f2tf32(v.w);
            }
        }
        // ---- B tile ----
#pragma unroll
        for (int i = 0; i < 4; i++) {
            const int k = b_k + i * 8;
            float4 v = *reinterpret_cast<const float4*>(B + (size_t)(k0 + k) * BN + b_q * 4);
            uint32_t* dst = &Bs[k][b_q * 4];
            dst[0] = f2tf32(v.x); dst[1] = f2tf32(v.y);
            dst[2] = f2tf32(v.z); dst[3] = f2tf32(v.w);
        }
        __syncthreads();

#pragma unroll
        for (int kk = 0; kk < BK / 8; kk++) {
            const int k8 = kk * 8;
            uint32_t a[2][4], b[4][2];
#pragma unroll
            for (int ma = 0; ma < 2; ma++) {
                const int m0 = wm * 32 + ma * 16 + g;
                const int m1 = m0 + 8;
                const int kq0 = (k8 + t) >> 2;
                const int kq1 = (k8 + t + 4) >> 2;
                a[ma][0] = As[m0][4 * (kq0 ^ (m0 & 7)) + t];
                a[ma][1] = As[m1][4 * (kq0 ^ (m1 & 7)) + t];
                a[ma][2] = As[m0][4 * (kq1 ^ (m0 & 7)) + t];
                a[ma][3] = As[m1][4 * (kq1 ^ (m1 & 7)) + t];
            }
#pragma unroll
            for (int na = 0; na < 4; na++) {
                const int n = wn * 32 + na * 8 + g;
                b[na][0] = Bs[k8 + t][n];
                b[na][1] = Bs[k8 + t + 4][n];
            }
#pragma unroll
            for (int ma = 0; ma < 2; ma++)
#pragma unroll
                for (int na = 0; na < 4; na++) {
                    float* c = acc[ma][na];
                    asm volatile(
                        "mma.sync.aligned.m16n8k8.row.col.f32.tf32.tf32.f32 "
                        "{%0,%1,%2,%3}, {%4,%5,%6,%7}, {%8,%9}, {%0,%1,%2,%3};"
                        : "+f"(c[0]), "+f"(c[1]), "+f"(c[2]), "+f"(c[3])
                        : "r"(a[ma][0]), "r"(a[ma][1]), "r"(a[ma][2]), "r"(a[ma][3]),
                          "r"(b[na][0]), "r"(b[na][1]));
                }
        }
        __syncthreads();
    }

#pragma unroll
    for (int ma = 0; ma < 2; ma++) {
        const int r0 = bm0 + wm * 32 + ma * 16 + g;
        const int r1 = r0 + 8;
#pragma unroll
        for (int na = 0; na < 4; na++) {
            const int col = wn * 32 + na * 8 + 2 * t;
            const float* c = acc[ma][na];
            if (r0 < M)
                *reinterpret_cast<float2*>(C + (size_t)r0 * BN + col) = make_float2(c[0], c[1]);
            if (r1 < M)
                *reinterpret_cast<float2*>(C + (size_t)r1 * BN + col) = make_float2(c[2], c[3]);
        }
    }
}

// ---------------------------------------------------------------------------
// Bucket scatter body: edges -> per-row buckets. 4 edges per thread.
// ---------------------------------------------------------------------------
__device__ __forceinline__ void scatter_body(
    const int* __restrict__ rows, const int* __restrict__ cols,
    const float* __restrict__ vals, int sb)
{
    int e = sb * 1024 + threadIdx.x;
#pragma unroll
    for (int k = 0; k < 4; k++, e += 256) {
        if (e < NEDGES) {
            const int r = rows[e];
            const int c = cols[e];
            const float v = vals[e];
            const int slot = atomicAdd(&g_cnt[r], 1);
            if (slot < CAP)
                g_edge[((size_t)r << 7) + slot] = make_int2(c, __float_as_int(v));
        }
    }
}

// ---------------------------------------------------------------------------
// Kernels
// ---------------------------------------------------------------------------
__global__ void zero_cnt_kernel()
{
    int i = blockIdx.x * blockDim.x + threadIdx.x;
    if (i < NNODES) g_cnt[i] = 0;
}

// Fused: blocks [0, GEMM_GRID) -> gemm1 (S1 = X @ W1);
//        blocks [GEMM_GRID, ...) -> edge bucket scatter. Disjoint data.
__global__ __launch_bounds__(256, 3) void gemm1_scatter_kernel(
    const float* __restrict__ A, const float* __restrict__ B,
    const int* __restrict__ rows, const int* __restrict__ cols,
    const float* __restrict__ vals)
{
    if (blockIdx.x < GEMM_GRID)
        gemm_tf32_body<FIN>(A, B, g_S1, blockIdx.x);
    else
        scatter_body(rows, cols, vals, blockIdx.x - GEMM_GRID);
}

__global__ __launch_bounds__(256, 3) void gemm2_kernel(const float* __restrict__ B)
{
    gemm_tf32_body<HID>(g_H, B, g_S2, blockIdx.x);   // S2 = H @ W2 (H already relu'd)
}

// ---------------------------------------------------------------------------
// Bucket SpMM with fused bias + relu: out[r] = relu(sum val*X[col] + bias)
// One warp per row, float4 per lane. Edge metadata read via warp-uniform
// int4 loads (L1 broadcast — no SHFL). x4 unroll keeps 4 gathers in flight.
// ---------------------------------------------------------------------------
template <int SRC, int DST>
__global__ __launch_bounds__(256) void spmm_kernel(
    const float* __restrict__ bias, float* __restrict__ outp)
{
    const int row  = (blockIdx.x * blockDim.x + threadIdx.x) >> 5;
    const int lane = threadIdx.x & 31;
    if (row >= NNODES) return;

    const float* X   = (SRC == 0) ? g_S1 : g_S2;
    float*       out = (DST == 0) ? g_H  : outp;

    const int deg = min(g_cnt[row], CAP);
    const int2* bucket = &g_edge[(size_t)row << 7];

    float4 acc = reinterpret_cast<const float4*>(bias)[lane];

    int i = 0;
    for (; i + 4 <= deg; i += 4) {
        // warp-uniform metadata loads (broadcast)
        const int4 m01 = *reinterpret_cast<const int4*>(&bucket[i]);
        const int4 m23 = *reinterpret_cast<const int4*>(&bucket[i + 2]);
        const float v0 = __int_as_float(m01.y);
        const float v1 = __int_as_float(m01.w);
        const float v2 = __int_as_float(m23.y);
        const float v3 = __int_as_float(m23.w);
        const float4 x0 = reinterpret_cast<const float4*>(X + (size_t)m01.x * HID)[lane];
        const float4 x1 = reinterpret_cast<const float4*>(X + (size_t)m01.z * HID)[lane];
        const float4 x2 = reinterpret_cast<const float4*>(X + (size_t)m23.x * HID)[lane];
        const float4 x3 = reinterpret_cast<const float4*>(X + (size_t)m23.z * HID)[lane];
        acc.x += v0 * x0.x; acc.y += v0 * x0.y; acc.z += v0 * x0.z; acc.w += v0 * x0.w;
        acc.x += v1 * x1.x; acc.y += v1 * x1.y; acc.z += v1 * x1.z; acc.w += v1 * x1.w;
        acc.x += v2 * x2.x; acc.y += v2 * x2.y; acc.z += v2 * x2.z; acc.w += v2 * x2.w;
        acc.x += v3 * x3.x; acc.y += v3 * x3.y; acc.z += v3 * x3.z; acc.w += v3 * x3.w;
    }
    for (; i < deg; i++) {
        const int2 ev = bucket[i];
        const float v = __int_as_float(ev.y);
        const float4 x = reinterpret_cast<const float4*>(X + (size_t)ev.x * HID)[lane];
        acc.x += v * x.x; acc.y += v * x.y;
        acc.z += v * x.z; acc.w += v * x.w;
    }

    acc.x = fmaxf(acc.x, 0.f); acc.y = fmaxf(acc.y, 0.f);
    acc.z = fmaxf(acc.z, 0.f); acc.w = fmaxf(acc.w, 0.f);
    reinterpret_cast<float4*>(out + (size_t)row * HID)[lane] = acc;
}

// ---------------------------------------------------------------------------
extern "C" void kernel_launch(void* const* d_in, const int* in_sizes, int n_in,
                              void* d_out, int out_size)
{
    const float* features = (const float*)d_in[0];
    const int*   adj_rows = (const int*)  d_in[1];
    const int*   adj_cols = (const int*)  d_in[2];
    const float* adj_vals = (const float*)d_in[3];
    const float* W1       = (const float*)d_in[4];
    const float* b1       = (const float*)d_in[5];
    const float* W2       = (const float*)d_in[6];
    const float* b2       = (const float*)d_in[7];
    float* out = (float*)d_out;

    const int node_grid = (NNODES + 255) / 256;
    const int spmm_grid = (NNODES * 32 + 255) / 256;

    zero_cnt_kernel<<<node_grid, 256>>>();
    gemm1_scatter_kernel<<<GEMM_GRID + SCAT_GRID, 256>>>(
        features, W1, adj_rows, adj_cols, adj_vals);

    spmm_kernel<0, 0><<<spmm_grid, 256>>>(b1, nullptr);

    gemm2_kernel<<<GEMM_GRID, 256>>>(W2);
    spmm_kernel<1, 1><<<spmm_grid, 256>>>(b2, out);
}

// round 12
// speedup vs baseline: 1.1657x; 1.1657x over previous
#include <cuda_runtime.h>
#include <cstdint>

#define NNODES 50000
#define NEDGES 800000
#define FIN 256
#define HID 128
#define CAP 128              // bucket capacity per row (Poisson(16) edges/row)
#define GEMM_GRID ((NNODES + 127) / 128)                 // 391 (BM=128)
#define SCAT_GRID ((NEDGES + 1023) / 1024)               // 782 (256 thr x 4 edges)

// Scratch (no cudaMalloc); device symbols so kernel_launch is pure launches.
__device__ float g_S1[NNODES * HID];     // X @ W1
__device__ float g_H [NNODES * HID];     // relu(A @ S1 + b1)
__device__ float g_S2[NNODES * HID];     // H @ W2
__device__ int   g_cnt[NNODES];          // per-row edge count (bucket fill)
__device__ int2  g_edge[(size_t)NNODES * CAP];  // (col, val-bits) buckets

// pack two floats into a bf16x2 register: lo = first (even k), hi = second
__device__ __forceinline__ uint32_t pack_bf16(float lo, float hi)
{
    uint32_t u;
    asm("cvt.rn.bf16x2.f32 %0, %1, %2;" : "=r"(u) : "f"(hi), "f"(lo));
    return u;
}

// ---------------------------------------------------------------------------
// bf16 tensor GEMM body: C[M,128] = A[M,K] @ B[K,128], fp32 accumulate.
// CTA 128x128, BK=32, 8 warps (2m x 4n), warp tile 64x32,
// mma.sync.m16n8k16.row.col.f32.bf16.bf16.f32 — half the MMA + A-LDS count
// of the tf32 version (issue-bound kernel).
// A smem: packed bf16x2 pairs, [128][20] u32 (frag banks 20g+t: conflict-free).
// B smem: fp32 [32][132]    (frag banks 8t+g: conflict-free; packed at load).
// Register prefetch of tile k+1 overlaps compute of tile k (R10-proven).
// ---------------------------------------------------------------------------
template <int K>
__device__ __forceinline__ void gemm_bf16_body(
    const float* __restrict__ A, const float* __restrict__ B,
    float* __restrict__ C, int bx)
{
    constexpr int BM = 128, BN = 128, BK = 32;
    constexpr int M = NNODES;
    constexpr int NT = K / BK;
    __shared__ uint32_t As[BM][20];       // bf16x2 pairs: As[m][p] = (k=2p, 2p+1)
    __shared__ float    Bs[BK][BN + 4];

    const int tid  = threadIdx.x;
    const int wid  = tid >> 5;
    const int lane = tid & 31;
    const int g    = lane >> 2;
    const int t    = lane & 3;
    const int wm   = wid >> 2;            // 0..1 -> m offset wm*64
    const int wn   = wid & 3;             // 0..3 -> n offset wn*32
    const int bm0  = bx * BM;

    float acc[4][4][4];
#pragma unroll
    for (int i = 0; i < 4; i++)
#pragma unroll
        for (int j = 0; j < 4; j++)
#pragma unroll
            for (int e = 0; e < 4; e++) acc[i][j][e] = 0.f;

    const int a_row0 = tid >> 3;          // +i*32
    const int a_q    = tid & 7;           // float4 index: k = 4q
    const int b_k    = tid >> 5;          // +i*8
    const int b_q    = tid & 31;

    float4 pa[4], pb[4];

    auto load_tile = [&](int k0) {
#pragma unroll
        for (int i = 0; i < 4; i++) {
            const int gr = bm0 + a_row0 + i * 32;
            pa[i] = (gr < M)
                ? *reinterpret_cast<const float4*>(A + (size_t)gr * K + k0 + a_q * 4)
                : make_float4(0.f, 0.f, 0.f, 0.f);
        }
#pragma unroll
        for (int i = 0; i < 4; i++) {
            const int k = b_k + i * 8;
            pb[i] = *reinterpret_cast<const float4*>(B + (size_t)(k0 + k) * BN + b_q * 4);
        }
    };

    auto store_tile = [&]() {
#pragma unroll
        for (int i = 0; i < 4; i++) {
            const int row = a_row0 + i * 32;
            As[row][2 * a_q]     = pack_bf16(pa[i].x, pa[i].y);
            As[row][2 * a_q + 1] = pack_bf16(pa[i].z, pa[i].w);
        }
#pragma unroll
        for (int i = 0; i < 4; i++) {
            const int k = b_k + i * 8;
            *reinterpret_cast<float4*>(&Bs[k][b_q * 4]) = pb[i];
        }
    };

    load_tile(0);

    for (int ti = 0; ti < NT; ti++) {
        store_tile();
        __syncthreads();
        if (ti + 1 < NT) load_tile((ti + 1) * BK);   // overlaps compute below

#pragma unroll
        for (int ks = 0; ks < 2; ks++) {             // two k16 steps per BK=32
            const int k16 = ks * 16;
            const int ph  = ks * 8;                  // pair base = k16/2
            uint32_t a[4][4], b[4][2];
#pragma unroll
            for (int ma = 0; ma < 4; ma++) {
                const int m0 = wm * 64 + ma * 16 + g;
                const int m1 = m0 + 8;
                a[ma][0] = As[m0][ph + t];
                a[ma][1] = As[m1][ph + t];
                a[ma][2] = As[m0][ph + 4 + t];
                a[ma][3] = As[m1][ph + 4 + t];
            }
#pragma unroll
            for (int na = 0; na < 4; na++) {
                const int n = wn * 32 + na * 8 + g;
                b[na][0] = pack_bf16(Bs[k16 + 2 * t][n],     Bs[k16 + 2 * t + 1][n]);
                b[na][1] = pack_bf16(Bs[k16 + 8 + 2 * t][n], Bs[k16 + 9 + 2 * t][n]);
            }
#pragma unroll
            for (int ma = 0; ma < 4; ma++)
#pragma unroll
                for (int na = 0; na < 4; na++) {
                    float* c = acc[ma][na];
                    asm volatile(
                        "mma.sync.aligned.m16n8k16.row.col.f32.bf16.bf16.f32 "
                        "{%0,%1,%2,%3}, {%4,%5,%6,%7}, {%8,%9}, {%0,%1,%2,%3};"
                        : "+f"(c[0]), "+f"(c[1]), "+f"(c[2]), "+f"(c[3])
                        : "r"(a[ma][0]), "r"(a[ma][1]), "r"(a[ma][2]), "r"(a[ma][3]),
                          "r"(b[na][0]), "r"(b[na][1]));
                }
        }
        __syncthreads();
    }

#pragma unroll
    for (int ma = 0; ma < 4; ma++) {
        const int r0 = bm0 + wm * 64 + ma * 16 + g;
        const int r1 = r0 + 8;
#pragma unroll
        for (int na = 0; na < 4; na++) {
            const int col = wn * 32 + na * 8 + 2 * t;
            const float* c = acc[ma][na];
            if (r0 < M)
                *reinterpret_cast<float2*>(C + (size_t)r0 * BN + col) = make_float2(c[0], c[1]);
            if (r1 < M)
                *reinterpret_cast<float2*>(C + (size_t)r1 * BN + col) = make_float2(c[2], c[3]);
        }
    }
}

// ---------------------------------------------------------------------------
// Bucket scatter body: edges -> per-row buckets. 4 edges per thread.
// ---------------------------------------------------------------------------
__device__ __forceinline__ void scatter_body(
    const int* __restrict__ rows, const int* __restrict__ cols,
    const float* __restrict__ vals, int sb)
{
    int e = sb * 1024 + threadIdx.x;
#pragma unroll
    for (int k = 0; k < 4; k++, e += 256) {
        if (e < NEDGES) {
            const int r = rows[e];
            const int c = cols[e];
            const float v = vals[e];
            const int slot = atomicAdd(&g_cnt[r], 1);
            if (slot < CAP)
                g_edge[((size_t)r << 7) + slot] = make_int2(c, __float_as_int(v));
        }
    }
}

// ---------------------------------------------------------------------------
// Kernels
// ---------------------------------------------------------------------------
__global__ void zero_cnt_kernel()
{
    int i = blockIdx.x * blockDim.x + threadIdx.x;
    if (i < NNODES) g_cnt[i] = 0;
}

// Fused: blocks [0, GEMM_GRID) -> gemm1 (S1 = X @ W1);
//        blocks [GEMM_GRID, ...) -> edge bucket scatter. Disjoint data.
__global__ __launch_bounds__(256) void gemm1_scatter_kernel(
    const float* __restrict__ A, const float* __restrict__ B,
    const int* __restrict__ rows, const int* __restrict__ cols,
    const float* __restrict__ vals)
{
    if (blockIdx.x < GEMM_GRID)
        gemm_bf16_body<FIN>(A, B, g_S1, blockIdx.x);
    else
        scatter_body(rows, cols, vals, blockIdx.x - GEMM_GRID);
}

__global__ __launch_bounds__(256) void gemm2_kernel(const float* __restrict__ B)
{
    gemm_bf16_body<HID>(g_H, B, g_S2, blockIdx.x);   // S2 = H @ W2 (H already relu'd)
}

// ---------------------------------------------------------------------------
// Bucket SpMM with fused bias + relu: out[r] = relu(sum val*X[col] + bias)
// One warp per row, float4 per lane. Edge metadata read via warp-uniform
// int4 loads (L1 broadcast — no SHFL). x4 unroll keeps 4 gathers in flight.
// ---------------------------------------------------------------------------
template <int SRC, int DST>
__global__ __launch_bounds__(256) void spmm_kernel(
    const float* __restrict__ bias, float* __restrict__ outp)
{
    const int row  = (blockIdx.x * blockDim.x + threadIdx.x) >> 5;
    const int lane = threadIdx.x & 31;
    if (row >= NNODES) return;

    const float* X   = (SRC == 0) ? g_S1 : g_S2;
    float*       out = (DST == 0) ? g_H  : outp;

    const int deg = min(g_cnt[row], CAP);
    const int2* bucket = &g_edge[(size_t)row << 7];

    float4 acc = reinterpret_cast<const float4*>(bias)[lane];

    int i = 0;
    for (; i + 4 <= deg; i += 4) {
        const int4 m01 = *reinterpret_cast<const int4*>(&bucket[i]);
        const int4 m23 = *reinterpret_cast<const int4*>(&bucket[i + 2]);
        const float v0 = __int_as_float(m01.y);
        const float v1 = __int_as_float(m01.w);
        const float v2 = __int_as_float(m23.y);
        const float v3 = __int_as_float(m23.w);
        const float4 x0 = reinterpret_cast<const float4*>(X + (size_t)m01.x * HID)[lane];
        const float4 x1 = reinterpret_cast<const float4*>(X + (size_t)m01.z * HID)[lane];
        const float4 x2 = reinterpret_cast<const float4*>(X + (size_t)m23.x * HID)[lane];
        const float4 x3 = reinterpret_cast<const float4*>(X + (size_t)m23.z * HID)[lane];
        acc.x += v0 * x0.x; acc.y += v0 * x0.y; acc.z += v0 * x0.z; acc.w += v0 * x0.w;
        acc.x += v1 * x1.x; acc.y += v1 * x1.y; acc.z += v1 * x1.z; acc.w += v1 * x1.w;
        acc.x += v2 * x2.x; acc.y += v2 * x2.y; acc.z += v2 * x2.z; acc.w += v2 * x2.w;
        acc.x += v3 * x3.x; acc.y += v3 * x3.y; acc.z += v3 * x3.z; acc.w += v3 * x3.w;
    }
    for (; i < deg; i++) {
        const int2 ev = bucket[i];
        const float v = __int_as_float(ev.y);
        const float4 x = reinterpret_cast<const float4*>(X + (size_t)ev.x * HID)[lane];
        acc.x += v * x.x; acc.y += v * x.y;
        acc.z += v * x.z; acc.w += v * x.w;
    }

    acc.x = fmaxf(acc.x, 0.f); acc.y = fmaxf(acc.y, 0.f);
    acc.z = fmaxf(acc.z, 0.f); acc.w = fmaxf(acc.w, 0.f);
    reinterpret_cast<float4*>(out + (size_t)row * HID)[lane] = acc;
}

// ---------------------------------------------------------------------------
extern "C" void kernel_launch(void* const* d_in, const int* in_sizes, int n_in,
                              void* d_out, int out_size)
{
    const float* features = (const float*)d_in[0];
    const int*   adj_rows = (const int*)  d_in[1];
    const int*   adj_cols = (const int*)  d_in[2];
    const float* adj_vals = (const float*)d_in[3];
    const float* W1       = (const float*)d_in[4];
    const float* b1       = (const float*)d_in[5];
    const float* W2       = (const float*)d_in[6];
    const float* b2       = (const float*)d_in[7];
    float* out = (float*)d_out;

    const int node_grid = (NNODES + 255) / 256;
    const int spmm_grid = (NNODES * 32 + 255) / 256;

    zero_cnt_kernel<<<node_grid, 256>>>();
    gemm1_scatter_kernel<<<GEMM_GRID + SCAT_GRID, 256>>>(
        features, W1, adj_rows, adj_cols, adj_vals);

    spmm_kernel<0, 0><<<spmm_grid, 256>>>(b1, nullptr);

    gemm2_kernel<<<GEMM_GRID, 256>>>(W2);
    spmm_kernel<1, 1><<<spmm_grid, 256>>>(b2, out);
}

// round 13
// speedup vs baseline: 1.4064x; 1.2064x over previous
#include <cuda_runtime.h>
#include <cuda_fp16.h>
#include <cstdint>

#define NNODES 50000
#define NEDGES 800000
#define FIN 256
#define HID 128
#define CAP 128              // bucket capacity per row (Poisson(16) edges/row)
#define GEMM_GRID ((NNODES + 127) / 128)                 // 391 (BM=128)
#define SCAT_GRID ((NEDGES + 1023) / 1024)               // 782 (256 thr x 4 edges)

// Scratch (no cudaMalloc); device symbols so kernel_launch is pure launches.
__device__ __half    g_S1h[(size_t)NNODES * HID];   // X @ W1          (fp16)
__device__ uint32_t  g_Hb [(size_t)NNODES * HID/2]; // relu(A@S1+b1)   (bf16x2 pairs)
__device__ __half    g_S2h[(size_t)NNODES * HID];   // H @ W2          (fp16)
__device__ int       g_cnt[NNODES];                 // per-row edge count
__device__ int2      g_edge[(size_t)NNODES * CAP];  // (col, val-bits) buckets

// pack two floats into a bf16x2 register: lo = first (even k), hi = second
__device__ __forceinline__ uint32_t pack_bf16(float lo, float hi)
{
    uint32_t u;
    asm("cvt.rn.bf16x2.f32 %0, %1, %2;" : "=r"(u) : "f"(hi), "f"(lo));
    return u;
}

// ---------------------------------------------------------------------------
// GEMM1: S1[M,128] = X[M,256] @ W1[256,128], bf16 mma m16n8k16, fp32 accum,
// fp16 output. CTA 128x128, BK=32, 8 warps, warp tile 64x32.
// A smem: bf16x2 pairs [128][20] u32 (frag banks 20g+t conflict-free).
// B smem: fp32 [32][132] (frag banks conflict-free; packed at frag load).
// Register prefetch of tile k+1 overlaps compute of tile k.
// ---------------------------------------------------------------------------
__device__ __forceinline__ void gemm1_body(
    const float* __restrict__ A, const float* __restrict__ B,
    __half* __restrict__ C, int bx)
{
    constexpr int BM = 128, BN = 128, BK = 32, K = FIN;
    constexpr int M = NNODES;
    constexpr int NT = K / BK;
    __shared__ uint32_t As[BM][20];
    __shared__ float    Bs[BK][BN + 4];

    const int tid  = threadIdx.x;
    const int wid  = tid >> 5;
    const int lane = tid & 31;
    const int g    = lane >> 2;
    const int t    = lane & 3;
    const int wm   = wid >> 2;
    const int wn   = wid & 3;
    const int bm0  = bx * BM;

    float acc[4][4][4];
#pragma unroll
    for (int i = 0; i < 4; i++)
#pragma unroll
        for (int j = 0; j < 4; j++)
#pragma unroll
            for (int e = 0; e < 4; e++) acc[i][j][e] = 0.f;

    const int a_row0 = tid >> 3;          // +i*32
    const int a_q    = tid & 7;           // float4 idx: k = 4q
    const int b_k    = tid >> 5;          // +i*8
    const int b_q    = tid & 31;

    float4 pa[4], pb[4];

    auto load_tile = [&](int k0) {
#pragma unroll
        for (int i = 0; i < 4; i++) {
            const int gr = bm0 + a_row0 + i * 32;
            pa[i] = (gr < M)
                ? *reinterpret_cast<const float4*>(A + (size_t)gr * K + k0 + a_q * 4)
                : make_float4(0.f, 0.f, 0.f, 0.f);
        }
#pragma unroll
        for (int i = 0; i < 4; i++) {
            const int k = b_k + i * 8;
            pb[i] = *reinterpret_cast<const float4*>(B + (size_t)(k0 + k) * BN + b_q * 4);
        }
    };

    auto store_tile = [&]() {
#pragma unroll
        for (int i = 0; i < 4; i++) {
            const int row = a_row0 + i * 32;
            As[row][2 * a_q]     = pack_bf16(pa[i].x, pa[i].y);
            As[row][2 * a_q + 1] = pack_bf16(pa[i].z, pa[i].w);
        }
#pragma unroll
        for (int i = 0; i < 4; i++) {
            const int k = b_k + i * 8;
            *reinterpret_cast<float4*>(&Bs[k][b_q * 4]) = pb[i];
        }
    };

    load_tile(0);

    for (int ti = 0; ti < NT; ti++) {
        store_tile();
        __syncthreads();
        if (ti + 1 < NT) load_tile((ti + 1) * BK);

#pragma unroll
        for (int ks = 0; ks < 2; ks++) {
            const int k16 = ks * 16;
            const int ph  = ks * 8;
            uint32_t a[4][4], b[4][2];
#pragma unroll
            for (int ma = 0; ma < 4; ma++) {
                const int m0 = wm * 64 + ma * 16 + g;
                const int m1 = m0 + 8;
                a[ma][0] = As[m0][ph + t];
                a[ma][1] = As[m1][ph + t];
                a[ma][2] = As[m0][ph + 4 + t];
                a[ma][3] = As[m1][ph + 4 + t];
            }
#pragma unroll
            for (int na = 0; na < 4; na++) {
                const int n = wn * 32 + na * 8 + g;
                b[na][0] = pack_bf16(Bs[k16 + 2 * t][n],     Bs[k16 + 2 * t + 1][n]);
                b[na][1] = pack_bf16(Bs[k16 + 8 + 2 * t][n], Bs[k16 + 9 + 2 * t][n]);
            }
#pragma unroll
            for (int ma = 0; ma < 4; ma++)
#pragma unroll
                for (int na = 0; na < 4; na++) {
                    float* c = acc[ma][na];
                    asm volatile(
                        "mma.sync.aligned.m16n8k16.row.col.f32.bf16.bf16.f32 "
                        "{%0,%1,%2,%3}, {%4,%5,%6,%7}, {%8,%9}, {%0,%1,%2,%3};"
                        : "+f"(c[0]), "+f"(c[1]), "+f"(c[2]), "+f"(c[3])
                        : "r"(a[ma][0]), "r"(a[ma][1]), "r"(a[ma][2]), "r"(a[ma][3]),
                          "r"(b[na][0]), "r"(b[na][1]));
                }
        }
        __syncthreads();
    }

    // fp16 epilogue: c[0],c[1] are adjacent columns -> one half2 store.
#pragma unroll
    for (int ma = 0; ma < 4; ma++) {
        const int r0 = bm0 + wm * 64 + ma * 16 + g;
        const int r1 = r0 + 8;
#pragma unroll
        for (int na = 0; na < 4; na++) {
            const int col = wn * 32 + na * 8 + 2 * t;
            const float* c = acc[ma][na];
            if (r0 < M)
                *reinterpret_cast<__half2*>(C + (size_t)r0 * BN + col) =
                    __floats2half2_rn(c[0], c[1]);
            if (r1 < M)
                *reinterpret_cast<__half2*>(C + (size_t)r1 * BN + col) =
                    __floats2half2_rn(c[2], c[3]);
        }
    }
}

// ---------------------------------------------------------------------------
// GEMM2: S2[M,128] = H[M,128](bf16 pairs) @ W2[128,128], fp16 output.
// A is already bf16x2-packed in g_Hb — loaded straight into smem, no cvt.
// ---------------------------------------------------------------------------
__device__ __forceinline__ void gemm2_body(
    const float* __restrict__ B, __half* __restrict__ C, int bx)
{
    constexpr int BM = 128, BN = 128, BK = 32, K = HID;
    constexpr int M = NNODES;
    constexpr int NT = K / BK;                 // 4
    __shared__ uint32_t As[BM][20];
    __shared__ float    Bs[BK][BN + 4];

    const int tid  = threadIdx.x;
    const int wid  = tid >> 5;
    const int lane = tid & 31;
    const int g    = lane >> 2;
    const int t    = lane & 3;
    const int wm   = wid >> 2;
    const int wn   = wid & 3;
    const int bm0  = bx * BM;

    float acc[4][4][4];
#pragma unroll
    for (int i = 0; i < 4; i++)
#pragma unroll
        for (int j = 0; j < 4; j++)
#pragma unroll
            for (int e = 0; e < 4; e++) acc[i][j][e] = 0.f;

    // A: per tile, each row needs 16 u32 pair-words; 2 threads/row x 2 uint4.
    const int a_row = tid >> 1;           // 0..127
    const int a_c   = (tid & 1) * 8;      // word offset 0 or 8
    const int b_k   = tid >> 5;
    const int b_q   = tid & 31;

    uint4 pa2[2];
    float4 pb[4];

    auto load_tile = [&](int ti) {
        const int gr = bm0 + a_row;
        if (gr < M) {
            const uint32_t* hrow = g_Hb + (size_t)gr * (HID / 2) + ti * 16 + a_c;
            pa2[0] = *reinterpret_cast<const uint4*>(hrow);
            pa2[1] = *reinterpret_cast<const uint4*>(hrow + 4);
        } else {
            pa2[0] = make_uint4(0, 0, 0, 0);
            pa2[1] = make_uint4(0, 0, 0, 0);
        }
#pragma unroll
        for (int i = 0; i < 4; i++) {
            const int k = b_k + i * 8;
            pb[i] = *reinterpret_cast<const float4*>(B + (size_t)(ti * BK + k) * BN + b_q * 4);
        }
    };

    auto store_tile = [&]() {
        uint32_t* dst = &As[a_row][a_c];
        dst[0] = pa2[0].x; dst[1] = pa2[0].y; dst[2] = pa2[0].z; dst[3] = pa2[0].w;
        dst[4] = pa2[1].x; dst[5] = pa2[1].y; dst[6] = pa2[1].z; dst[7] = pa2[1].w;
#pragma unroll
        for (int i = 0; i < 4; i++) {
            const int k = b_k + i * 8;
            *reinterpret_cast<float4*>(&Bs[k][b_q * 4]) = pb[i];
        }
    };

    load_tile(0);

    for (int ti = 0; ti < NT; ti++) {
        store_tile();
        __syncthreads();
        if (ti + 1 < NT) load_tile(ti + 1);

#pragma unroll
        for (int ks = 0; ks < 2; ks++) {
            const int k16 = ks * 16;
            const int ph  = ks * 8;
            uint32_t a[4][4], b[4][2];
#pragma unroll
            for (int ma = 0; ma < 4; ma++) {
                const int m0 = wm * 64 + ma * 16 + g;
                const int m1 = m0 + 8;
                a[ma][0] = As[m0][ph + t];
                a[ma][1] = As[m1][ph + t];
                a[ma][2] = As[m0][ph + 4 + t];
                a[ma][3] = As[m1][ph + 4 + t];
            }
#pragma unroll
            for (int na = 0; na < 4; na++) {
                const int n = wn * 32 + na * 8 + g;
                b[na][0] = pack_bf16(Bs[k16 + 2 * t][n],     Bs[k16 + 2 * t + 1][n]);
                b[na][1] = pack_bf16(Bs[k16 + 8 + 2 * t][n], Bs[k16 + 9 + 2 * t][n]);
            }
#pragma unroll
            for (int ma = 0; ma < 4; ma++)
#pragma unroll
                for (int na = 0; na < 4; na++) {
                    float* c = acc[ma][na];
                    asm volatile(
                        "mma.sync.aligned.m16n8k16.row.col.f32.bf16.bf16.f32 "
                        "{%0,%1,%2,%3}, {%4,%5,%6,%7}, {%8,%9}, {%0,%1,%2,%3};"
                        : "+f"(c[0]), "+f"(c[1]), "+f"(c[2]), "+f"(c[3])
                        : "r"(a[ma][0]), "r"(a[ma][1]), "r"(a[ma][2]), "r"(a[ma][3]),
                          "r"(b[na][0]), "r"(b[na][1]));
                }
        }
        __syncthreads();
    }

#pragma unroll
    for (int ma = 0; ma < 4; ma++) {
        const int r0 = bm0 + wm * 64 + ma * 16 + g;
        const int r1 = r0 + 8;
#pragma unroll
        for (int na = 0; na < 4; na++) {
            const int col = wn * 32 + na * 8 + 2 * t;
            const float* c = acc[ma][na];
            if (r0 < M)
                *reinterpret_cast<__half2*>(C + (size_t)r0 * BN + col) =
                    __floats2half2_rn(c[0], c[1]);
            if (r1 < M)
                *reinterpret_cast<__half2*>(C + (size_t)r1 * BN + col) =
                    __floats2half2_rn(c[2], c[3]);
        }
    }
}

// ---------------------------------------------------------------------------
// Bucket scatter body: edges -> per-row buckets. 4 edges per thread.
// ---------------------------------------------------------------------------
__device__ __forceinline__ void scatter_body(
    const int* __restrict__ rows, const int* __restrict__ cols,
    const float* __restrict__ vals, int sb)
{
    int e = sb * 1024 + threadIdx.x;
#pragma unroll
    for (int k = 0; k < 4; k++, e += 256) {
        if (e < NEDGES) {
            const int r = rows[e];
            const int c = cols[e];
            const float v = vals[e];
            const int slot = atomicAdd(&g_cnt[r], 1);
            if (slot < CAP)
                g_edge[((size_t)r << 7) + slot] = make_int2(c, __float_as_int(v));
        }
    }
}

__global__ void zero_cnt_kernel()
{
    int i = blockIdx.x * blockDim.x + threadIdx.x;
    if (i < NNODES) g_cnt[i] = 0;
}

// Fused: blocks [0, GEMM_GRID) -> gemm1; blocks [GEMM_GRID, ...) -> scatter.
__global__ __launch_bounds__(256) void gemm1_scatter_kernel(
    const float* __restrict__ A, const float* __restrict__ B,
    const int* __restrict__ rows, const int* __restrict__ cols,
    const float* __restrict__ vals)
{
    if (blockIdx.x < GEMM_GRID)
        gemm1_body(A, B, g_S1h, blockIdx.x);
    else
        scatter_body(rows, cols, vals, blockIdx.x - GEMM_GRID);
}

__global__ __launch_bounds__(256) void gemm2_kernel(const float* __restrict__ B)
{
    gemm2_body(B, g_S2h, blockIdx.x);
}

// ---------------------------------------------------------------------------
// Bucket SpMM, fp16 gather (half traffic), fp32 accumulate, fused bias+relu.
// One warp per row; lane l owns cols 4l..4l+3 (8B fp16 per lane per gather).
// LAYER 1: X=g_S1h -> out=g_Hb (bf16 pairs). LAYER 2: X=g_S2h -> fp32 out.
// ---------------------------------------------------------------------------
__device__ __forceinline__ float4 gather_h4(const __half* __restrict__ X,
                                            int c, int lane)
{
    const uint2 q = reinterpret_cast<const uint2*>(X + (size_t)c * HID)[lane];
    const float2 f01 = __half22float2(*reinterpret_cast<const __half2*>(&q.x));
    const float2 f23 = __half22float2(*reinterpret_cast<const __half2*>(&q.y));
    return make_float4(f01.x, f01.y, f23.x, f23.y);
}

template <int LAYER>
__global__ __launch_bounds__(256) void spmm_kernel(
    const float* __restrict__ bias, float* __restrict__ outp)
{
    const int row  = (blockIdx.x * blockDim.x + threadIdx.x) >> 5;
    const int lane = threadIdx.x & 31;
    if (row >= NNODES) return;

    const __half* X = (LAYER == 1) ? g_S1h : g_S2h;

    const int deg = min(g_cnt[row], CAP);
    const int2* bucket = &g_edge[(size_t)row << 7];

    float4 acc = reinterpret_cast<const float4*>(bias)[lane];

    int i = 0;
    for (; i + 4 <= deg; i += 4) {
        const int4 m01 = *reinterpret_cast<const int4*>(&bucket[i]);
        const int4 m23 = *reinterpret_cast<const int4*>(&bucket[i + 2]);
        const float v0 = __int_as_float(m01.y);
        const float v1 = __int_as_float(m01.w);
        const float v2 = __int_as_float(m23.y);
        const float v3 = __int_as_float(m23.w);
        const float4 x0 = gather_h4(X, m01.x, lane);
        const float4 x1 = gather_h4(X, m01.z, lane);
        const float4 x2 = gather_h4(X, m23.x, lane);
        const float4 x3 = gather_h4(X, m23.z, lane);
        acc.x += v0 * x0.x; acc.y += v0 * x0.y; acc.z += v0 * x0.z; acc.w += v0 * x0.w;
        acc.x += v1 * x1.x; acc.y += v1 * x1.y; acc.z += v1 * x1.z; acc.w += v1 * x1.w;
        acc.x += v2 * x2.x; acc.y += v2 * x2.y; acc.z += v2 * x2.z; acc.w += v2 * x2.w;
        acc.x += v3 * x3.x; acc.y += v3 * x3.y; acc.z += v3 * x3.z; acc.w += v3 * x3.w;
    }
    for (; i < deg; i++) {
        const int2 ev = bucket[i];
        const float v = __int_as_float(ev.y);
        const float4 x = gather_h4(X, ev.x, lane);
        acc.x += v * x.x; acc.y += v * x.y;
        acc.z += v * x.z; acc.w += v * x.w;
    }

    acc.x = fmaxf(acc.x, 0.f); acc.y = fmaxf(acc.y, 0.f);
    acc.z = fmaxf(acc.z, 0.f); acc.w = fmaxf(acc.w, 0.f);

    if (LAYER == 1) {
        // store H as bf16x2 pairs (cols 4l..4l+3 -> words 2l, 2l+1)
        uint2 p;
        p.x = pack_bf16(acc.x, acc.y);
        p.y = pack_bf16(acc.z, acc.w);
        reinterpret_cast<uint2*>(g_Hb + (size_t)row * (HID / 2))[lane] = p;
    } else {
        reinterpret_cast<float4*>(outp + (size_t)row * HID)[lane] = acc;
    }
}

// ---------------------------------------------------------------------------
extern "C" void kernel_launch(void* const* d_in, const int* in_sizes, int n_in,
                              void* d_out, int out_size)
{
    const float* features = (const float*)d_in[0];
    const int*   adj_rows = (const int*)  d_in[1];
    const int*   adj_cols = (const int*)  d_in[2];
    const float* adj_vals = (const float*)d_in[3];
    const float* W1       = (const float*)d_in[4];
    const float* b1       = (const float*)d_in[5];
    const float* W2       = (const float*)d_in[6];
    const float* b2       = (const float*)d_in[7];
    float* out = (float*)d_out;

    const int node_grid = (NNODES + 255) / 256;
    const int spmm_grid = (NNODES * 32 + 255) / 256;

    zero_cnt_kernel<<<node_grid, 256>>>();
    gemm1_scatter_kernel<<<GEMM_GRID + SCAT_GRID, 256>>>(
        features, W1, adj_rows, adj_cols, adj_vals);

    spmm_kernel<1><<<spmm_grid, 256>>>(b1, nullptr);

    gemm2_kernel<<<GEMM_GRID, 256>>>(W2);
    spmm_kernel<2><<<spmm_grid, 256>>>(b2, out);
}

// round 14
// speedup vs baseline: 1.4080x; 1.0012x over previous
#include <cuda_runtime.h>
#include <cuda_fp16.h>
#include <cstdint>

#define NNODES 50000
#define NEDGES 800000
#define FIN 256
#define HID 128
#define CAP 128              // bucket capacity per row (Poisson(16) edges/row)
#define GEMM_GRID ((NNODES + 127) / 128)                 // 391 (BM=128)
#define SCAT_GRID ((NEDGES + 1023) / 1024)               // 782 (256 thr x 4 edges)

// Scratch (no cudaMalloc); device symbols so kernel_launch is pure launches.
__device__ __half    g_S1h[(size_t)NNODES * HID];   // X @ W1          (fp16)
__device__ uint32_t  g_Hb [(size_t)NNODES * HID/2]; // relu(A@S1+b1)   (bf16x2 pairs)
__device__ __half    g_S2h[(size_t)NNODES * HID];   // H @ W2          (fp16)
__device__ int       g_cnt[NNODES];                 // per-row edge count (BSS=0;
                                                    // re-zeroed by spmm<2> each call)
__device__ int2      g_edge[(size_t)NNODES * CAP];  // (col, val-bits) buckets

// pack two floats into a bf16x2 register: lo = first (even k), hi = second
__device__ __forceinline__ uint32_t pack_bf16(float lo, float hi)
{
    uint32_t u;
    asm("cvt.rn.bf16x2.f32 %0, %1, %2;" : "=r"(u) : "f"(hi), "f"(lo));
    return u;
}

// ---------------------------------------------------------------------------
// Shared GEMM mainloop pieces. CTA 128x128, BK=32, 8 warps (2m x 4n),
// warp tile 64x32, mma.m16n8k16 bf16, fp32 accum, fp16 output.
// A smem: bf16x2 pairs [128][20] u32  (frag banks 20g+t: conflict-free).
// B smem: bf16x2 pairs [16][136] u32  (frag banks 8t+g+8na: conflict-free).
//   Bp[p][n] holds (k=2p, 2p+1) for column n — packed once at store time.
// Register prefetch of tile k+1 overlaps compute of tile k.
// ---------------------------------------------------------------------------
#define BP_STRIDE 136

// B gmem->reg: rows k0+2*pr, k0+2*pr+1 (pr = tid>>5 + 8j), float4 at col 4*(tid&31)
__device__ __forceinline__ void load_b_tile(
    const float* __restrict__ B, int k0, int tid, float4* pbE, float4* pbO)
{
    const int prb = tid >> 5;
    const int n4  = tid & 31;
#pragma unroll
    for (int j = 0; j < 2; j++) {
        const int kr = k0 + 2 * (prb + 8 * j);
        pbE[j] = *reinterpret_cast<const float4*>(B + (size_t)kr * 128 + n4 * 4);
        pbO[j] = *reinterpret_cast<const float4*>(B + (size_t)(kr + 1) * 128 + n4 * 4);
    }
}

__device__ __forceinline__ void store_b_tile(
    uint32_t (*Bp)[BP_STRIDE], int tid, const float4* pbE, const float4* pbO)
{
    const int prb = tid >> 5;
    const int n4  = tid & 31;
#pragma unroll
    for (int j = 0; j < 2; j++) {
        uint4 w;
        w.x = pack_bf16(pbE[j].x, pbO[j].x);
        w.y = pack_bf16(pbE[j].y, pbO[j].y);
        w.z = pack_bf16(pbE[j].z, pbO[j].z);
        w.w = pack_bf16(pbE[j].w, pbO[j].w);
        *reinterpret_cast<uint4*>(&Bp[prb + 8 * j][n4 * 4]) = w;
    }
}

// One BK=32 compute block (two k16 MMA steps)
__device__ __forceinline__ void mma_block(
    const uint32_t (*As)[20], const uint32_t (*Bp)[BP_STRIDE],
    float acc[4][4][4], int wm, int wn, int g, int t)
{
#pragma unroll
    for (int ks = 0; ks < 2; ks++) {
        const int ph = ks * 8;
        uint32_t a[4][4], b[4][2];
#pragma unroll
        for (int ma = 0; ma < 4; ma++) {
            const int m0 = wm * 64 + ma * 16 + g;
            const int m1 = m0 + 8;
            a[ma][0] = As[m0][ph + t];
            a[ma][1] = As[m1][ph + t];
            a[ma][2] = As[m0][ph + 4 + t];
            a[ma][3] = As[m1][ph + 4 + t];
        }
#pragma unroll
        for (int na = 0; na < 4; na++) {
            const int n = wn * 32 + na * 8 + g;
            b[na][0] = Bp[ph + t][n];
            b[na][1] = Bp[ph + 4 + t][n];
        }
#pragma unroll
        for (int ma = 0; ma < 4; ma++)
#pragma unroll
            for (int na = 0; na < 4; na++) {
                float* c = acc[ma][na];
                asm volatile(
                    "mma.sync.aligned.m16n8k16.row.col.f32.bf16.bf16.f32 "
                    "{%0,%1,%2,%3}, {%4,%5,%6,%7}, {%8,%9}, {%0,%1,%2,%3};"
                    : "+f"(c[0]), "+f"(c[1]), "+f"(c[2]), "+f"(c[3])
                    : "r"(a[ma][0]), "r"(a[ma][1]), "r"(a[ma][2]), "r"(a[ma][3]),
                      "r"(b[na][0]), "r"(b[na][1]));
            }
    }
}

__device__ __forceinline__ void gemm_epilogue(
    __half* __restrict__ C, const float acc[4][4][4],
    int bm0, int wm, int wn, int g, int t)
{
#pragma unroll
    for (int ma = 0; ma < 4; ma++) {
        const int r0 = bm0 + wm * 64 + ma * 16 + g;
        const int r1 = r0 + 8;
#pragma unroll
        for (int na = 0; na < 4; na++) {
            const int col = wn * 32 + na * 8 + 2 * t;
            const float* c = acc[ma][na];
            if (r0 < NNODES)
                *reinterpret_cast<__half2*>(C + (size_t)r0 * 128 + col) =
                    __floats2half2_rn(c[0], c[1]);
            if (r1 < NNODES)
                *reinterpret_cast<__half2*>(C + (size_t)r1 * 128 + col) =
                    __floats2half2_rn(c[2], c[3]);
        }
    }
}

// ---------------------------------------------------------------------------
// GEMM1: S1 = X[M,256](fp32) @ W1[256,128](fp32) -> fp16
// ---------------------------------------------------------------------------
__device__ __forceinline__ void gemm1_body(
    const float* __restrict__ A, const float* __restrict__ B,
    __half* __restrict__ C, int bx)
{
    constexpr int K = FIN, BK = 32, NT = K / BK;
    __shared__ uint32_t As[128][20];
    __shared__ uint32_t Bp[16][BP_STRIDE];

    const int tid  = threadIdx.x;
    const int wid  = tid >> 5;
    const int lane = tid & 31;
    const int g    = lane >> 2;
    const int t    = lane & 3;
    const int wm   = wid >> 2;
    const int wn   = wid & 3;
    const int bm0  = bx * 128;

    float acc[4][4][4];
#pragma unroll
    for (int i = 0; i < 4; i++)
#pragma unroll
        for (int j = 0; j < 4; j++)
#pragma unroll
            for (int e = 0; e < 4; e++) acc[i][j][e] = 0.f;

    const int a_row0 = tid >> 3;          // +i*32
    const int a_q    = tid & 7;           // float4 idx: k = 4q

    float4 pa[4], pbE[2], pbO[2];

    auto load_a = [&](int k0) {
#pragma unroll
        for (int i = 0; i < 4; i++) {
            const int gr = bm0 + a_row0 + i * 32;
            pa[i] = (gr < NNODES)
                ? *reinterpret_cast<const float4*>(A + (size_t)gr * K + k0 + a_q * 4)
                : make_float4(0.f, 0.f, 0.f, 0.f);
        }
    };
    auto store_a = [&]() {
#pragma unroll
        for (int i = 0; i < 4; i++) {
            const int row = a_row0 + i * 32;
            As[row][2 * a_q]     = pack_bf16(pa[i].x, pa[i].y);
            As[row][2 * a_q + 1] = pack_bf16(pa[i].z, pa[i].w);
        }
    };

    load_a(0);
    load_b_tile(B, 0, tid, pbE, pbO);

    for (int ti = 0; ti < NT; ti++) {
        store_a();
        store_b_tile(Bp, tid, pbE, pbO);
        __syncthreads();
        if (ti + 1 < NT) {
            load_a((ti + 1) * BK);
            load_b_tile(B, (ti + 1) * BK, tid, pbE, pbO);
        }
        mma_block(As, Bp, acc, wm, wn, g, t);
        __syncthreads();
    }
    gemm_epilogue(C, acc, bm0, wm, wn, g, t);
}

// ---------------------------------------------------------------------------
// GEMM2: S2 = H[M,128](bf16 pairs) @ W2[128,128](fp32) -> fp16
// A loaded straight from g_Hb (already packed), no conversion.
// ---------------------------------------------------------------------------
__device__ __forceinline__ void gemm2_body(
    const float* __restrict__ B, __half* __restrict__ C, int bx)
{
    constexpr int K = HID, BK = 32, NT = K / BK;   // 4 tiles
    __shared__ uint32_t As[128][20];
    __shared__ uint32_t Bp[16][BP_STRIDE];

    const int tid  = threadIdx.x;
    const int wid  = tid >> 5;
    const int lane = tid & 31;
    const int g    = lane >> 2;
    const int t    = lane & 3;
    const int wm   = wid >> 2;
    const int wn   = wid & 3;
    const int bm0  = bx * 128;

    float acc[4][4][4];
#pragma unroll
    for (int i = 0; i < 4; i++)
#pragma unroll
        for (int j = 0; j < 4; j++)
#pragma unroll
            for (int e = 0; e < 4; e++) acc[i][j][e] = 0.f;

    const int a_row = tid >> 1;           // 0..127
    const int a_c   = (tid & 1) * 8;      // word offset 0 or 8

    uint4 pa2[2];
    float4 pbE[2], pbO[2];

    auto load_a = [&](int ti) {
        const int gr = bm0 + a_row;
        if (gr < NNODES) {
            const uint32_t* hrow = g_Hb + (size_t)gr * (HID / 2) + ti * 16 + a_c;
            pa2[0] = *reinterpret_cast<const uint4*>(hrow);
            pa2[1] = *reinterpret_cast<const uint4*>(hrow + 4);
        } else {
            pa2[0] = make_uint4(0, 0, 0, 0);
            pa2[1] = make_uint4(0, 0, 0, 0);
        }
    };
    auto store_a = [&]() {
        uint32_t* dst = &As[a_row][a_c];
        dst[0] = pa2[0].x; dst[1] = pa2[0].y; dst[2] = pa2[0].z; dst[3] = pa2[0].w;
        dst[4] = pa2[1].x; dst[5] = pa2[1].y; dst[6] = pa2[1].z; dst[7] = pa2[1].w;
    };

    load_a(0);
    load_b_tile(B, 0, tid, pbE, pbO);

    for (int ti = 0; ti < NT; ti++) {
        store_a();
        store_b_tile(Bp, tid, pbE, pbO);
        __syncthreads();
        if (ti + 1 < NT) {
            load_a(ti + 1);
            load_b_tile(B, (ti + 1) * BK, tid, pbE, pbO);
        }
        mma_block(As, Bp, acc, wm, wn, g, t);
        __syncthreads();
    }
    gemm_epilogue(C, acc, bm0, wm, wn, g, t);
}

// ---------------------------------------------------------------------------
// Bucket scatter body: edges -> per-row buckets. 4 edges per thread.
// ---------------------------------------------------------------------------
__device__ __forceinline__ void scatter_body(
    const int* __restrict__ rows, const int* __restrict__ cols,
    const float* __restrict__ vals, int sb)
{
    int e = sb * 1024 + threadIdx.x;
#pragma unroll
    for (int k = 0; k < 4; k++, e += 256) {
        if (e < NEDGES) {
            const int r = rows[e];
            const int c = cols[e];
            const float v = vals[e];
            const int slot = atomicAdd(&g_cnt[r], 1);
            if (slot < CAP)
                g_edge[((size_t)r << 7) + slot] = make_int2(c, __float_as_int(v));
        }
    }
}

// Fused: blocks [0, GEMM_GRID) -> gemm1; blocks [GEMM_GRID, ...) -> scatter.
__global__ __launch_bounds__(256) void gemm1_scatter_kernel(
    const float* __restrict__ A, const float* __restrict__ B,
    const int* __restrict__ rows, const int* __restrict__ cols,
    const float* __restrict__ vals)
{
    if (blockIdx.x < GEMM_GRID)
        gemm1_body(A, B, g_S1h, blockIdx.x);
    else
        scatter_body(rows, cols, vals, blockIdx.x - GEMM_GRID);
}

__global__ __launch_bounds__(256) void gemm2_kernel(const float* __restrict__ B)
{
    gemm2_body(B, g_S2h, blockIdx.x);
}

// ---------------------------------------------------------------------------
// Bucket SpMM, fp16 gather, fp32 accumulate, fused bias+relu.
// One warp per row; lane l owns cols 4l..4l+3.
// LAYER 1: X=g_S1h -> g_Hb (bf16 pairs). LAYER 2: X=g_S2h -> fp32 out,
// then re-zeroes g_cnt[row] for the next graph replay.
// ---------------------------------------------------------------------------
__device__ __forceinline__ float4 gather_h4(const __half* __restrict__ X,
                                            int c, int lane)
{
    const uint2 q = reinterpret_cast<const uint2*>(X + (size_t)c * HID)[lane];
    const float2 f01 = __half22float2(*reinterpret_cast<const __half2*>(&q.x));
    const float2 f23 = __half22float2(*reinterpret_cast<const __half2*>(&q.y));
    return make_float4(f01.x, f01.y, f23.x, f23.y);
}

template <int LAYER>
__global__ __launch_bounds__(256) void spmm_kernel(
    const float* __restrict__ bias, float* __restrict__ outp)
{
    const int row  = (blockIdx.x * blockDim.x + threadIdx.x) >> 5;
    const int lane = threadIdx.x & 31;
    if (row >= NNODES) return;

    const __half* X = (LAYER == 1) ? g_S1h : g_S2h;

    const int deg = min(g_cnt[row], CAP);
    const int2* bucket = &g_edge[(size_t)row << 7];

    float4 acc = reinterpret_cast<const float4*>(bias)[lane];

    int i = 0;
    for (; i + 4 <= deg; i += 4) {
        const int4 m01 = *reinterpret_cast<const int4*>(&bucket[i]);
        const int4 m23 = *reinterpret_cast<const int4*>(&bucket[i + 2]);
        const float v0 = __int_as_float(m01.y);
        const float v1 = __int_as_float(m01.w);
        const float v2 = __int_as_float(m23.y);
        const float v3 = __int_as_float(m23.w);
        const float4 x0 = gather_h4(X, m01.x, lane);
        const float4 x1 = gather_h4(X, m01.z, lane);
        const float4 x2 = gather_h4(X, m23.x, lane);
        const float4 x3 = gather_h4(X, m23.z, lane);
        acc.x += v0 * x0.x; acc.y += v0 * x0.y; acc.z += v0 * x0.z; acc.w += v0 * x0.w;
        acc.x += v1 * x1.x; acc.y += v1 * x1.y; acc.z += v1 * x1.z; acc.w += v1 * x1.w;
        acc.x += v2 * x2.x; acc.y += v2 * x2.y; acc.z += v2 * x2.z; acc.w += v2 * x2.w;
        acc.x += v3 * x3.x; acc.y += v3 * x3.y; acc.z += v3 * x3.z; acc.w += v3 * x3.w;
    }
    for (; i < deg; i++) {
        const int2 ev = bucket[i];
        const float v = __int_as_float(ev.y);
        const float4 x = gather_h4(X, ev.x, lane);
        acc.x += v * x.x; acc.y += v * x.y;
        acc.z += v * x.z; acc.w += v * x.w;
    }

    acc.x = fmaxf(acc.x, 0.f); acc.y = fmaxf(acc.y, 0.f);
    acc.z = fmaxf(acc.z, 0.f); acc.w = fmaxf(acc.w, 0.f);

    if (LAYER == 1) {
        uint2 p;
        p.x = pack_bf16(acc.x, acc.y);
        p.y = pack_bf16(acc.z, acc.w);
        reinterpret_cast<uint2*>(g_Hb + (size_t)row * (HID / 2))[lane] = p;
    } else {
        reinterpret_cast<float4*>(outp + (size_t)row * HID)[lane] = acc;
        if (lane == 0) g_cnt[row] = 0;    // reset bucket counter for next replay
    }
}

// ---------------------------------------------------------------------------
extern "C" void kernel_launch(void* const* d_in, const int* in_sizes, int n_in,
                              void* d_out, int out_size)
{
    const float* features = (const float*)d_in[0];
    const int*   adj_rows = (const int*)  d_in[1];
    const int*   adj_cols = (const int*)  d_in[2];
    const float* adj_vals = (const float*)d_in[3];
    const float* W1       = (const float*)d_in[4];
    const float* b1       = (const float*)d_in[5];
    const float* W2       = (const float*)d_in[6];
    const float* b2       = (const float*)d_in[7];
    float* out = (float*)d_out;

    const int spmm_grid = (NNODES * 32 + 255) / 256;

    // g_cnt starts zeroed (BSS on first call; spmm<2> re-zeroes each call).
    gemm1_scatter_kernel<<<GEMM_GRID + SCAT_GRID, 256>>>(
        features, W1, adj_rows, adj_cols, adj_vals);

    spmm_kernel<1><<<spmm_grid, 256>>>(b1, nullptr);

    gemm2_kernel<<<GEMM_GRID, 256>>>(W2);
    spmm_kernel<2><<<spmm_grid, 256>>>(b2, out);
}

// round 15
// speedup vs baseline: 1.4632x; 1.0392x over previous
#include <cuda_runtime.h>
#include <cuda_fp16.h>
#include <cstdint>

#define NNODES 50000
#define NEDGES 800000
#define FIN 256
#define HID 128
#define CAP 128              // bucket capacity per row (Poisson(16) edges/row)
#define GEMM_GRID ((NNODES + 127) / 128)                 // 391 (BM=128)
#define SCAT_GRID ((NEDGES + 1023) / 1024)               // 782 (256 thr x 4 edges)

// Scratch (no cudaMalloc); device symbols so kernel_launch is pure launches.
__device__ __half    g_S1h[(size_t)NNODES * HID];   // X @ W1          (fp16)
__device__ uint32_t  g_Hb [(size_t)NNODES * HID/2]; // relu(A@S1+b1)   (bf16x2 pairs)
__device__ __half    g_S2h[(size_t)NNODES * HID];   // H @ W2          (fp16)
__device__ int       g_cnt[NNODES];                 // per-row edge count (BSS=0;
                                                    // re-zeroed by spmm<2> each call)
__device__ int2      g_edge[(size_t)NNODES * CAP];  // (col, val-bits) buckets

// pack two floats into a bf16x2 register: lo = first (even k), hi = second
__device__ __forceinline__ uint32_t pack_bf16(float lo, float hi)
{
    uint32_t u;
    asm("cvt.rn.bf16x2.f32 %0, %1, %2;" : "=r"(u) : "f"(hi), "f"(lo));
    return u;
}

// ---------------------------------------------------------------------------
// Shared GEMM mainloop pieces. CTA 128x128, BK=32, 8 warps (2m x 4n),
// warp tile 64x32, mma.m16n8k16 bf16, fp32 accum, fp16 output.
// A smem: bf16x2 pairs [128][20] u32  (frag banks 20g+t: conflict-free).
// B smem: bf16x2 pairs [16][136] u32  (frag banks 8t+g+8na: conflict-free).
// Register prefetch of tile k+1 overlaps compute of tile k.
// ---------------------------------------------------------------------------
#define BP_STRIDE 136

__device__ __forceinline__ void load_b_tile(
    const float* __restrict__ B, int k0, int tid, float4* pbE, float4* pbO)
{
    const int prb = tid >> 5;
    const int n4  = tid & 31;
#pragma unroll
    for (int j = 0; j < 2; j++) {
        const int kr = k0 + 2 * (prb + 8 * j);
        pbE[j] = *reinterpret_cast<const float4*>(B + (size_t)kr * 128 + n4 * 4);
        pbO[j] = *reinterpret_cast<const float4*>(B + (size_t)(kr + 1) * 128 + n4 * 4);
    }
}

__device__ __forceinline__ void store_b_tile(
    uint32_t (*Bp)[BP_STRIDE], int tid, const float4* pbE, const float4* pbO)
{
    const int prb = tid >> 5;
    const int n4  = tid & 31;
#pragma unroll
    for (int j = 0; j < 2; j++) {
        uint4 w;
        w.x = pack_bf16(pbE[j].x, pbO[j].x);
        w.y = pack_bf16(pbE[j].y, pbO[j].y);
        w.z = pack_bf16(pbE[j].z, pbO[j].z);
        w.w = pack_bf16(pbE[j].w, pbO[j].w);
        *reinterpret_cast<uint4*>(&Bp[prb + 8 * j][n4 * 4]) = w;
    }
}

__device__ __forceinline__ void mma_block(
    const uint32_t (*As)[20], const uint32_t (*Bp)[BP_STRIDE],
    float acc[4][4][4], int wm, int wn, int g, int t)
{
#pragma unroll
    for (int ks = 0; ks < 2; ks++) {
        const int ph = ks * 8;
        uint32_t a[4][4], b[4][2];
#pragma unroll
        for (int ma = 0; ma < 4; ma++) {
            const int m0 = wm * 64 + ma * 16 + g;
            const int m1 = m0 + 8;
            a[ma][0] = As[m0][ph + t];
            a[ma][1] = As[m1][ph + t];
            a[ma][2] = As[m0][ph + 4 + t];
            a[ma][3] = As[m1][ph + 4 + t];
        }
#pragma unroll
        for (int na = 0; na < 4; na++) {
            const int n = wn * 32 + na * 8 + g;
            b[na][0] = Bp[ph + t][n];
            b[na][1] = Bp[ph + 4 + t][n];
        }
#pragma unroll
        for (int ma = 0; ma < 4; ma++)
#pragma unroll
            for (int na = 0; na < 4; na++) {
                float* c = acc[ma][na];
                asm volatile(
                    "mma.sync.aligned.m16n8k16.row.col.f32.bf16.bf16.f32 "
                    "{%0,%1,%2,%3}, {%4,%5,%6,%7}, {%8,%9}, {%0,%1,%2,%3};"
                    : "+f"(c[0]), "+f"(c[1]), "+f"(c[2]), "+f"(c[3])
                    : "r"(a[ma][0]), "r"(a[ma][1]), "r"(a[ma][2]), "r"(a[ma][3]),
                      "r"(b[na][0]), "r"(b[na][1]));
            }
    }
}

__device__ __forceinline__ void gemm_epilogue(
    __half* __restrict__ C, const float acc[4][4][4],
    int bm0, int wm, int wn, int g, int t)
{
#pragma unroll
    for (int ma = 0; ma < 4; ma++) {
        const int r0 = bm0 + wm * 64 + ma * 16 + g;
        const int r1 = r0 + 8;
#pragma unroll
        for (int na = 0; na < 4; na++) {
            const int col = wn * 32 + na * 8 + 2 * t;
            const float* c = acc[ma][na];
            if (r0 < NNODES)
                *reinterpret_cast<__half2*>(C + (size_t)r0 * 128 + col) =
                    __floats2half2_rn(c[0], c[1]);
            if (r1 < NNODES)
                *reinterpret_cast<__half2*>(C + (size_t)r1 * 128 + col) =
                    __floats2half2_rn(c[2], c[3]);
        }
    }
}

// ---------------------------------------------------------------------------
// GEMM1: S1 = X[M,256](fp32) @ W1[256,128](fp32) -> fp16
// ---------------------------------------------------------------------------
__device__ __forceinline__ void gemm1_body(
    const float* __restrict__ A, const float* __restrict__ B,
    __half* __restrict__ C, int bx)
{
    constexpr int K = FIN, BK = 32, NT = K / BK;
    __shared__ uint32_t As[128][20];
    __shared__ uint32_t Bp[16][BP_STRIDE];

    const int tid  = threadIdx.x;
    const int wid  = tid >> 5;
    const int lane = tid & 31;
    const int g    = lane >> 2;
    const int t    = lane & 3;
    const int wm   = wid >> 2;
    const int wn   = wid & 3;
    const int bm0  = bx * 128;

    float acc[4][4][4];
#pragma unroll
    for (int i = 0; i < 4; i++)
#pragma unroll
        for (int j = 0; j < 4; j++)
#pragma unroll
            for (int e = 0; e < 4; e++) acc[i][j][e] = 0.f;

    const int a_row0 = tid >> 3;
    const int a_q    = tid & 7;

    float4 pa[4], pbE[2], pbO[2];

    auto load_a = [&](int k0) {
#pragma unroll
        for (int i = 0; i < 4; i++) {
            const int gr = bm0 + a_row0 + i * 32;
            pa[i] = (gr < NNODES)
                ? *reinterpret_cast<const float4*>(A + (size_t)gr * K + k0 + a_q * 4)
                : make_float4(0.f, 0.f, 0.f, 0.f);
        }
    };
    auto store_a = [&]() {
#pragma unroll
        for (int i = 0; i < 4; i++) {
            const int row = a_row0 + i * 32;
            As[row][2 * a_q]     = pack_bf16(pa[i].x, pa[i].y);
            As[row][2 * a_q + 1] = pack_bf16(pa[i].z, pa[i].w);
        }
    };

    load_a(0);
    load_b_tile(B, 0, tid, pbE, pbO);

    for (int ti = 0; ti < NT; ti++) {
        store_a();
        store_b_tile(Bp, tid, pbE, pbO);
        __syncthreads();
        if (ti + 1 < NT) {
            load_a((ti + 1) * BK);
            load_b_tile(B, (ti + 1) * BK, tid, pbE, pbO);
        }
        mma_block(As, Bp, acc, wm, wn, g, t);
        __syncthreads();
    }
    gemm_epilogue(C, acc, bm0, wm, wn, g, t);
}

// ---------------------------------------------------------------------------
// GEMM2: S2 = H[M,128](bf16 pairs) @ W2[128,128](fp32) -> fp16
// ---------------------------------------------------------------------------
__device__ __forceinline__ void gemm2_body(
    const float* __restrict__ B, __half* __restrict__ C, int bx)
{
    constexpr int BK = 32, NT = HID / BK;   // 4 tiles
    __shared__ uint32_t As[128][20];
    __shared__ uint32_t Bp[16][BP_STRIDE];

    const int tid  = threadIdx.x;
    const int wid  = tid >> 5;
    const int lane = tid & 31;
    const int g    = lane >> 2;
    const int t    = lane & 3;
    const int wm   = wid >> 2;
    const int wn   = wid & 3;
    const int bm0  = bx * 128;

    float acc[4][4][4];
#pragma unroll
    for (int i = 0; i < 4; i++)
#pragma unroll
        for (int j = 0; j < 4; j++)
#pragma unroll
            for (int e = 0; e < 4; e++) acc[i][j][e] = 0.f;

    const int a_row = tid >> 1;
    const int a_c   = (tid & 1) * 8;

    uint4 pa2[2];
    float4 pbE[2], pbO[2];

    auto load_a = [&](int ti) {
        const int gr = bm0 + a_row;
        if (gr < NNODES) {
            const uint32_t* hrow = g_Hb + (size_t)gr * (HID / 2) + ti * 16 + a_c;
            pa2[0] = *reinterpret_cast<const uint4*>(hrow);
            pa2[1] = *reinterpret_cast<const uint4*>(hrow + 4);
        } else {
            pa2[0] = make_uint4(0, 0, 0, 0);
            pa2[1] = make_uint4(0, 0, 0, 0);
        }
    };
    auto store_a = [&]() {
        uint32_t* dst = &As[a_row][a_c];
        dst[0] = pa2[0].x; dst[1] = pa2[0].y; dst[2] = pa2[0].z; dst[3] = pa2[0].w;
        dst[4] = pa2[1].x; dst[5] = pa2[1].y; dst[6] = pa2[1].z; dst[7] = pa2[1].w;
    };

    load_a(0);
    load_b_tile(B, 0, tid, pbE, pbO);

    for (int ti = 0; ti < NT; ti++) {
        store_a();
        store_b_tile(Bp, tid, pbE, pbO);
        __syncthreads();
        if (ti + 1 < NT) {
            load_a(ti + 1);
            load_b_tile(B, (ti + 1) * BK, tid, pbE, pbO);
        }
        mma_block(As, Bp, acc, wm, wn, g, t);
        __syncthreads();
    }
    gemm_epilogue(C, acc, bm0, wm, wn, g, t);
}

// ---------------------------------------------------------------------------
// Bucket scatter body: edges -> per-row buckets. 4 edges per thread.
// ---------------------------------------------------------------------------
__device__ __forceinline__ void scatter_body(
    const int* __restrict__ rows, const int* __restrict__ cols,
    const float* __restrict__ vals, int sb)
{
    int e = sb * 1024 + threadIdx.x;
#pragma unroll
    for (int k = 0; k < 4; k++, e += 256) {
        if (e < NEDGES) {
            const int r = rows[e];
            const int c = cols[e];
            const float v = vals[e];
            const int slot = atomicAdd(&g_cnt[r], 1);
            if (slot < CAP)
                g_edge[((size_t)r << 7) + slot] = make_int2(c, __float_as_int(v));
        }
    }
}

// Fused: blocks [0, GEMM_GRID) -> gemm1; blocks [GEMM_GRID, ...) -> scatter.
__global__ __launch_bounds__(256) void gemm1_scatter_kernel(
    const float* __restrict__ A, const float* __restrict__ B,
    const int* __restrict__ rows, const int* __restrict__ cols,
    const float* __restrict__ vals)
{
    if (blockIdx.x < GEMM_GRID)
        gemm1_body(A, B, g_S1h, blockIdx.x);
    else
        scatter_body(rows, cols, vals, blockIdx.x - GEMM_GRID);
}

__global__ __launch_bounds__(256) void gemm2_kernel(const float* __restrict__ B)
{
    gemm2_body(B, g_S2h, blockIdx.x);
}

// ---------------------------------------------------------------------------
// Bucket SpMM, fp16 gather, fp32 accumulate, fused bias+relu.
// One warp per row; lane l owns cols 4l..4l+3 (one uint2 per gather).
// x8 unrolled block: 4 independent metadata int4 loads then 8 independent
// row gathers in flight per lane (MLP ~12) before the convert+FMA chain.
// LAYER 1: X=g_S1h -> g_Hb (bf16 pairs). LAYER 2: X=g_S2h -> fp32 out,
// then re-zeroes g_cnt[row] for the next graph replay.
// ---------------------------------------------------------------------------
__device__ __forceinline__ void edge_fma(float4& acc, float v, uint2 q)
{
    const float2 f01 = __half22float2(*reinterpret_cast<const __half2*>(&q.x));
    const float2 f23 = __half22float2(*reinterpret_cast<const __half2*>(&q.y));
    acc.x += v * f01.x; acc.y += v * f01.y;
    acc.z += v * f23.x; acc.w += v * f23.y;
}

template <int LAYER>
__global__ __launch_bounds__(256) void spmm_kernel(
    const float* __restrict__ bias, float* __restrict__ outp)
{
    const int row  = (blockIdx.x * blockDim.x + threadIdx.x) >> 5;
    const int lane = threadIdx.x & 31;
    if (row >= NNODES) return;

    const uint2* Xr = reinterpret_cast<const uint2*>(
        (LAYER == 1) ? g_S1h : g_S2h);           // 32 uint2 per row

    const int deg = min(g_cnt[row], CAP);
    const int2* bucket = &g_edge[(size_t)row << 7];

    float4 acc = reinterpret_cast<const float4*>(bias)[lane];

    int i = 0;
    for (; i + 8 <= deg; i += 8) {
        const int4 m0 = *reinterpret_cast<const int4*>(&bucket[i]);
        const int4 m1 = *reinterpret_cast<const int4*>(&bucket[i + 2]);
        const int4 m2 = *reinterpret_cast<const int4*>(&bucket[i + 4]);
        const int4 m3 = *reinterpret_cast<const int4*>(&bucket[i + 6]);
        uint2 q[8];
        q[0] = Xr[(size_t)m0.x * 32 + lane];
        q[1] = Xr[(size_t)m0.z * 32 + lane];
        q[2] = Xr[(size_t)m1.x * 32 + lane];
        q[3] = Xr[(size_t)m1.z * 32 + lane];
        q[4] = Xr[(size_t)m2.x * 32 + lane];
        q[5] = Xr[(size_t)m2.z * 32 + lane];
        q[6] = Xr[(size_t)m3.x * 32 + lane];
        q[7] = Xr[(size_t)m3.z * 32 + lane];
        edge_fma(acc, __int_as_float(m0.y), q[0]);
        edge_fma(acc, __int_as_float(m0.w), q[1]);
        edge_fma(acc, __int_as_float(m1.y), q[2]);
        edge_fma(acc, __int_as_float(m1.w), q[3]);
        edge_fma(acc, __int_as_float(m2.y), q[4]);
        edge_fma(acc, __int_as_float(m2.w), q[5]);
        edge_fma(acc, __int_as_float(m3.y), q[6]);
        edge_fma(acc, __int_as_float(m3.w), q[7]);
    }
    for (; i + 4 <= deg; i += 4) {
        const int4 m0 = *reinterpret_cast<const int4*>(&bucket[i]);
        const int4 m1 = *reinterpret_cast<const int4*>(&bucket[i + 2]);
        uint2 q[4];
        q[0] = Xr[(size_t)m0.x * 32 + lane];
        q[1] = Xr[(size_t)m0.z * 32 + lane];
        q[2] = Xr[(size_t)m1.x * 32 + lane];
        q[3] = Xr[(size_t)m1.z * 32 + lane];
        edge_fma(acc, __int_as_float(m0.y), q[0]);
        edge_fma(acc, __int_as_float(m0.w), q[1]);
        edge_fma(acc, __int_as_float(m1.y), q[2]);
        edge_fma(acc, __int_as_float(m1.w), q[3]);
    }
    for (; i < deg; i++) {
        const int2 ev = bucket[i];
        edge_fma(acc, __int_as_float(ev.y), Xr[(size_t)ev.x * 32 + lane]);
    }

    acc.x = fmaxf(acc.x, 0.f); acc.y = fmaxf(acc.y, 0.f);
    acc.z = fmaxf(acc.z, 0.f); acc.w = fmaxf(acc.w, 0.f);

    if (LAYER == 1) {
        uint2 p;
        p.x = pack_bf16(acc.x, acc.y);
        p.y = pack_bf16(acc.z, acc.w);
        reinterpret_cast<uint2*>(g_Hb + (size_t)row * (HID / 2))[lane] = p;
    } else {
        reinterpret_cast<float4*>(outp + (size_t)row * HID)[lane] = acc;
        if (lane == 0) g_cnt[row] = 0;    // reset bucket counter for next replay
    }
}

// ---------------------------------------------------------------------------
extern "C" void kernel_launch(void* const* d_in, const int* in_sizes, int n_in,
                              void* d_out, int out_size)
{
    const float* features = (const float*)d_in[0];
    const int*   adj_rows = (const int*)  d_in[1];
    const int*   adj_cols = (const int*)  d_in[2];
    const float* adj_vals = (const float*)d_in[3];
    const float* W1       = (const float*)d_in[4];
    const float* b1       = (const float*)d_in[5];
    const float* W2       = (const float*)d_in[6];
    const float* b2       = (const float*)d_in[7];
    float* out = (float*)d_out;

    const int spmm_grid = (NNODES * 32 + 255) / 256;

    // g_cnt starts zeroed (BSS on first call; spmm<2> re-zeroes each call).
    gemm1_scatter_kernel<<<GEMM_GRID + SCAT_GRID, 256>>>(
        features, W1, adj_rows, adj_cols, adj_vals);

    spmm_kernel<1><<<spmm_grid, 256>>>(b1, nullptr);

    gemm2_kernel<<<GEMM_GRID, 256>>>(W2);
    spmm_kernel<2><<<spmm_grid, 256>>>(b2, out);
}